// round 15
// baseline (speedup 1.0000x reference)
#include <cuda_runtime.h>
#include <cuda_fp16.h>
#include <math.h>
#include <stdint.h>

// Problem constants
#define SEQ    2048
#define DIN    4096
#define DOUT   4096
#define NH     32
#define NKV    8
#define HD     128
#define GROUP  4

// Scratch buffers
__device__ float  g_Q[SEQ * DOUT];
__device__ float  g_K[SEQ * (NKV * HD)];
__device__ float  g_V[SEQ * (NKV * HD)];
__device__ __half g_Kh[SEQ * (NKV * HD)];
__device__ __half g_Vth[(NKV * HD) * SEQ];
__device__ __half g_ctxh[SEQ * DOUT];
__device__ __half g_xh[SEQ * DIN];
__device__ __half g_Wqh[DOUT * DIN];
__device__ __half g_Wkh[(NKV * HD) * DIN];
__device__ __half g_Wvh[(NKV * HD) * DIN];
__device__ __half g_Woh[DOUT * DOUT];

// fp16 mma
__device__ __forceinline__ void mma_f16(float* c, const uint32_t* a, const uint32_t* b) {
    asm volatile(
        "mma.sync.aligned.m16n8k16.row.col.f32.f16.f16.f32 "
        "{%0,%1,%2,%3}, {%4,%5,%6,%7}, {%8,%9}, {%0,%1,%2,%3};"
        : "+f"(c[0]), "+f"(c[1]), "+f"(c[2]), "+f"(c[3])
        : "r"(a[0]), "r"(a[1]), "r"(a[2]), "r"(a[3]), "r"(b[0]), "r"(b[1]));
}

__device__ __forceinline__ void ldsm4(uint32_t* r, uint32_t addr) {
    asm volatile("ldmatrix.sync.aligned.m8n8.x4.shared.b16 {%0,%1,%2,%3}, [%4];"
        : "=r"(r[0]), "=r"(r[1]), "=r"(r[2]), "=r"(r[3]) : "r"(addr));
}

__device__ __forceinline__ uint32_t smem_u32(const void* p) {
    uint32_t a;
    asm("{ .reg .u64 t; cvta.to.shared.u64 t, %1; cvt.u32.u64 %0, t; }"
        : "=r"(a) : "l"(p));
    return a;
}

__device__ __forceinline__ void cp16(uint32_t dst, const void* src) {
    asm volatile("cp.async.cg.shared.global [%0], [%1], 16;"
                 :: "r"(dst), "l"(src) : "memory");
}
#define CP_COMMIT() asm volatile("cp.async.commit_group;" ::: "memory")
#define CP_WAIT(n)  asm volatile("cp.async.wait_group %0;" :: "n"(n) : "memory")

__device__ __forceinline__ uint32_t pack_h2(float a, float b) {
    __half2 h = __floats2half2_rn(a, b);
    return *(uint32_t*)&h;
}

// ---------------------------------------------------------------------------
// Batched fp32 -> fp16 conversion (one launch)
// ---------------------------------------------------------------------------
#define N4_X   ((SEQ * DIN) / 4)
#define N4_WQ  ((DOUT * DIN) / 4)
#define N4_WK  (((NKV * HD) * DIN) / 4)
#define N4_WV  (((NKV * HD) * DIN) / 4)
#define N4_WO  ((DOUT * DOUT) / 4)
#define N4_TOT (N4_X + N4_WQ + N4_WK + N4_WV + N4_WO)

__global__ __launch_bounds__(256) void round_f16_all(
    const float* __restrict__ x,  const float* __restrict__ Wq,
    const float* __restrict__ Wk, const float* __restrict__ Wv,
    const float* __restrict__ Wo,
    __half* __restrict__ xh,  __half* __restrict__ Wqh,
    __half* __restrict__ Wkh, __half* __restrict__ Wvh,
    __half* __restrict__ Woh)
{
    for (int i = blockIdx.x * blockDim.x + threadIdx.x; i < N4_TOT;
         i += gridDim.x * blockDim.x) {
        const float* in;
        __half* out;
        int j = i;
        if (j < N4_X)                 { in = x;  out = xh; }
        else if ((j -= N4_X)  < N4_WQ){ in = Wq; out = Wqh; }
        else if ((j -= N4_WQ) < N4_WK){ in = Wk; out = Wkh; }
        else if ((j -= N4_WK) < N4_WV){ in = Wv; out = Wvh; }
        else { j -= N4_WV;              in = Wo; out = Woh; }
        float4 v = *(const float4*)(in + (size_t)j * 4);
        __half2 h0 = __floats2half2_rn(v.x, v.y);
        __half2 h1 = __floats2half2_rn(v.z, v.w);
        *(uint2*)(out + (size_t)j * 4) =
            make_uint2(*(uint32_t*)&h0, *(uint32_t*)&h1);
    }
}

// ---------------------------------------------------------------------------
// V transpose: [SEQ][1024] fp32 -> [1024][SEQ] fp16
// ---------------------------------------------------------------------------
__global__ __launch_bounds__(256) void vtrans(
    const float* __restrict__ V, __half* __restrict__ Vt)
{
    __shared__ float t[32][33];
    const int s0 = blockIdx.x * 32;
    const int c0 = blockIdx.y * 32;
    const int tx = threadIdx.x & 31;
    const int ty = threadIdx.x >> 5;
#pragma unroll
    for (int i = ty; i < 32; i += 8)
        t[i][tx] = V[(size_t)(s0 + i) * (NKV * HD) + c0 + tx];
    __syncthreads();
#pragma unroll
    for (int i = ty; i < 32; i += 8)
        Vt[(size_t)(c0 + i) * SEQ + s0 + tx] = __float2half_rn(t[tx][i]);
}

// ===========================================================================
// fp16 GEMM core — Round 15: 256x128 CTA tile, 256 threads (8 warps, 4Mx2N,
// warp tile 64x64 unchanged), ldmatrix frags, single barrier per K-chunk.
// Stage: A 256x128B (32KB) + B 128x128B (16KB) = 48KB, 3 stages.
// ===========================================================================
#define GS 3
#define STAGE_BYTES 49152
#define GEMM_SMEM (GS * STAGE_BYTES)

__device__ __forceinline__ void gemm_core_h(
    const __half* __restrict__ A, const __half* __restrict__ B,
    float* __restrict__ C, int K, int ldc, int bm)
{
    extern __shared__ char sbuf[];
    const uint32_t sbase = smem_u32(sbuf);
    const int tid  = threadIdx.x;
    const int lane = tid & 31;
    const int warp = tid >> 5;
    const int gID  = lane >> 2;
    const int tig  = lane & 3;
    const int wm   = (warp & 3) * 64;    // 4 M-warps over 256 rows
    const int wn   = (warp >> 2) * 64;   // 2 N-warps over 128 cols

    const int fr = tid >> 3;             // 0..31
    const int fc = tid & 7;

    const int l7    = lane & 7;
    const int aRowL = l7 + ((lane >> 3) & 1) * 8;
    const int aChO  = lane >> 4;
    const int bRowL = l7 + (lane >> 4) * 8;
    const int bChO  = (lane >> 3) & 1;

    float acc[4][8][4];
#pragma unroll
    for (int mi = 0; mi < 4; mi++)
#pragma unroll
        for (int ni = 0; ni < 8; ni++)
#pragma unroll
            for (int j = 0; j < 4; j++) acc[mi][ni][j] = 0.f;

    const int nK = K >> 6;

    auto fill = [&](int st, int kt) {
        const uint32_t dA = sbase + st * STAGE_BYTES;
        const uint32_t dB = dA + 32768;
        const __half* gA = A + (size_t)bm * K + kt * 64;
        const __half* gB = B + (size_t)kt * 64;
#pragma unroll
        for (int i = 0; i < 8; i++) {     // A: 256 rows
            const int r = fr + i * 32;
            const uint32_t sw = (uint32_t)(r * 128 + ((fc ^ (r & 7)) * 16));
            cp16(dA + sw, gA + (size_t)r * K + fc * 8);
        }
#pragma unroll
        for (int i = 0; i < 4; i++) {     // B: 128 rows
            const int r = fr + i * 32;
            const uint32_t sw = (uint32_t)(r * 128 + ((fc ^ (r & 7)) * 16));
            cp16(dB + sw, gB + (size_t)r * K + fc * 8);
        }
    };

    // prologue: stages 0..GS-2
#pragma unroll
    for (int s = 0; s < GS - 1; s++) {
        if (s < nK) fill(s, s);
        CP_COMMIT();
    }

    for (int kt = 0; kt < nK; kt++) {
        CP_WAIT(1);            // stage kt's group complete (2 outstanding -> 1)
        __syncthreads();       // all warps done computing stage (kt+GS-1)%GS's buffer

        const int nxt = kt + GS - 1;
        if (nxt < nK) fill(nxt % GS, nxt);
        CP_COMMIT();

        const uint32_t sa = sbase + (kt % GS) * STAGE_BYTES;
        const uint32_t sb = sa + 32768;
        uint32_t aBase[4], bBase[4];
#pragma unroll
        for (int mi = 0; mi < 4; mi++)
            aBase[mi] = sa + (uint32_t)((wm + mi * 16 + aRowL) * 128);
#pragma unroll
        for (int nj = 0; nj < 4; nj++)
            bBase[nj] = sb + (uint32_t)((wn + nj * 16 + bRowL) * 128);

#pragma unroll
        for (int kk = 0; kk < 4; kk++) {
            const int chA = 2 * kk + aChO;
            const int chB = 2 * kk + bChO;
            const uint32_t swA = (uint32_t)((chA ^ l7) << 4);
            const uint32_t swB = (uint32_t)((chB ^ l7) << 4);

            uint32_t af[4][4], bf[8][2];
#pragma unroll
            for (int mi = 0; mi < 4; mi++)
                ldsm4(af[mi], aBase[mi] + swA);
#pragma unroll
            for (int nj = 0; nj < 4; nj++) {
                uint32_t tmp[4];
                ldsm4(tmp, bBase[nj] + swB);
                bf[2 * nj][0]     = tmp[0];
                bf[2 * nj][1]     = tmp[1];
                bf[2 * nj + 1][0] = tmp[2];
                bf[2 * nj + 1][1] = tmp[3];
            }
#pragma unroll
            for (int mi = 0; mi < 4; mi++)
#pragma unroll
                for (int ni = 0; ni < 8; ni++)
                    mma_f16(acc[mi][ni], af[mi], bf[ni]);
        }
    }

#pragma unroll
    for (int mi = 0; mi < 4; mi++) {
        const int r0 = bm + wm + mi * 16 + gID;
#pragma unroll
        for (int ni = 0; ni < 8; ni++) {
            const int c0 = wn + ni * 8 + tig * 2;
            const float* c = acc[mi][ni];
            *(float2*)(C + (size_t)r0 * ldc + c0)       = make_float2(c[0], c[1]);
            *(float2*)(C + (size_t)(r0 + 8) * ldc + c0) = make_float2(c[2], c[3]);
        }
    }
}

__global__ __launch_bounds__(256, 1) void gemm_qkv(
    const __half* __restrict__ x,
    const __half* __restrict__ Wq, const __half* __restrict__ Wk,
    const __half* __restrict__ Wv,
    float* __restrict__ Q, float* __restrict__ Ko, float* __restrict__ Vo)
{
    const int bn = blockIdx.x;
    const int bm = blockIdx.y * 256;
    const __half* B;
    float* C;
    int ldc, coff;
    if (bn < 32)      { B = Wq; C = Q;  ldc = DOUT; coff = bn * 128; }
    else if (bn < 40) { B = Wk; C = Ko; ldc = NKV * HD; coff = (bn - 32) * 128; }
    else              { B = Wv; C = Vo; ldc = NKV * HD; coff = (bn - 40) * 128; }
    gemm_core_h(x, B + (size_t)coff * DIN, C + coff, DIN, ldc, bm);
}

__global__ __launch_bounds__(256, 1) void gemm_nt(
    const __half* __restrict__ A, const __half* __restrict__ B,
    float* __restrict__ C, int K, int N)
{
    const int coff = blockIdx.x * 128;
    gemm_core_h(A, B + (size_t)coff * K, C + coff, K, N, blockIdx.y * 256);
}

// RoPE for K: fp32 in, fp16 out
__global__ __launch_bounds__(256) void rope_k_h(
    const float* __restrict__ T, __half* __restrict__ Th,
    const float* __restrict__ cosT, const float* __restrict__ sinT)
{
    int idx = blockIdx.x * blockDim.x + threadIdx.x;
    int total = SEQ * NKV * 64;
    if (idx >= total) return;
    int d = idx & 63;
    int h = (idx >> 6) % NKV;
    int s = idx / (64 * NKV);

    const float* row = T + (size_t)s * (NKV * HD) + h * HD;
    __half* rowh = Th + (size_t)s * (NKV * HD) + h * HD;
    float x1 = row[d];
    float x2 = row[d + 64];
    rowh[d]      = __float2half_rn(fmaf(x1, cosT[s * HD + d],      -x2 * sinT[s * HD + d]));
    rowh[d + 64] = __float2half_rn(fmaf(x2, cosT[s * HD + d + 64],  x1 * sinT[s * HD + d + 64]));
}

// ---------------------------------------------------------------------------
// fp16 flash attention with fused Q-RoPE (Round 14 — validated)
// ---------------------------------------------------------------------------
#define BQ   128
#define BKV  64
#define PSH  72
#define ATT_STAGE 32768
#define ATT_SMEM  (2 * ATT_STAGE + BQ * PSH * 2)

__global__ __launch_bounds__(256, 1) void attn_mma(
    const float* __restrict__ Q, const __half* __restrict__ Kh,
    const __half* __restrict__ Vt, __half* __restrict__ ctx,
    const float* __restrict__ cosT, const float* __restrict__ sinT)
{
    const int qb  = gridDim.x - 1 - blockIdx.x;
    const int h   = blockIdx.y;
    const int hk  = h >> 2;
    const int tid = threadIdx.x;
    const int lane = tid & 31;
    const int warp = tid >> 5;
    const int gID  = lane >> 2;
    const int tig  = lane & 3;
    const int wrow = warp * 16;

    extern __shared__ char smc[];
    const uint32_t sbase = smem_u32(smc);
    __half* Psh = (__half*)(smc + 2 * ATT_STAGE);

    const float scale = 0.08838834764831845f;

    auto fill = [&](int buf, int kb) {
        {
            const int r  = tid >> 2;
            const uint32_t kdst = sbase + buf * ATT_STAGE + r * 256;
            const __half* ksrc = Kh + (size_t)(kb * BKV + r) * (NKV * HD) + hk * HD;
#pragma unroll
            for (int j = 0; j < 4; j++) {
                const int ch = (tid & 3) * 4 + j;
                cp16(kdst + (uint32_t)((ch ^ (r & 7)) << 4), ksrc + ch * 8);
            }
        }
        {
            const int r  = tid >> 1;
            const uint32_t vdst = sbase + buf * ATT_STAGE + 16384 + r * 128;
            const __half* vsrc = Vt + (size_t)(hk * HD + r) * SEQ + kb * BKV;
#pragma unroll
            for (int j = 0; j < 4; j++) {
                const int ch = (tid & 1) * 4 + j;
                cp16(vdst + (uint32_t)((ch ^ (r & 7)) << 4), vsrc + ch * 8);
            }
        }
    };

    // ---- Q fragments: load raw, apply RoPE in registers, pack fp16 ----
    uint32_t qf[8][4];
    {
        const int s0 = qb * BQ + wrow + gID;
        const int s1 = s0 + 8;
        const float* q0 = Q + (size_t)s0 * DOUT + h * HD;
        const float* q1 = Q + (size_t)s1 * DOUT + h * HD;

        float r0[8][4], r1[8][4];
#pragma unroll
        for (int kk = 0; kk < 8; kk++) {
            const int k = kk * 16;
            r0[kk][0] = q0[k + 2 * tig];     r0[kk][1] = q0[k + 2 * tig + 1];
            r0[kk][2] = q0[k + 8 + 2 * tig]; r0[kk][3] = q0[k + 9 + 2 * tig];
            r1[kk][0] = q1[k + 2 * tig];     r1[kk][1] = q1[k + 2 * tig + 1];
            r1[kk][2] = q1[k + 8 + 2 * tig]; r1[kk][3] = q1[k + 9 + 2 * tig];
        }
        const int off[4] = {2 * tig, 2 * tig + 1, 8 + 2 * tig, 9 + 2 * tig};
#pragma unroll
        for (int kk = 0; kk < 4; kk++) {
#pragma unroll
            for (int j = 0; j < 4; j++) {
                const int d = kk * 16 + off[j];
                const float cL  = cosT[s0 * HD + d],      sL  = sinT[s0 * HD + d];
                const float cH  = cosT[s0 * HD + d + 64], sH  = sinT[s0 * HD + d + 64];
                const float cL1 = cosT[s1 * HD + d],      sL1 = sinT[s1 * HD + d];
                const float cH1 = cosT[s1 * HD + d + 64], sH1 = sinT[s1 * HD + d + 64];
                float lo, hi;
                lo = r0[kk][j]; hi = r0[kk + 4][j];
                r0[kk][j]     = fmaf(lo, cL, -hi * sL);
                r0[kk + 4][j] = fmaf(hi, cH,  lo * sH);
                lo = r1[kk][j]; hi = r1[kk + 4][j];
                r1[kk][j]     = fmaf(lo, cL1, -hi * sL1);
                r1[kk + 4][j] = fmaf(hi, cH1,  lo * sH1);
            }
        }
#pragma unroll
        for (int kk = 0; kk < 8; kk++) {
            qf[kk][0] = pack_h2(r0[kk][0] * scale, r0[kk][1] * scale);
            qf[kk][1] = pack_h2(r1[kk][0] * scale, r1[kk][1] * scale);
            qf[kk][2] = pack_h2(r0[kk][2] * scale, r0[kk][3] * scale);
            qf[kk][3] = pack_h2(r1[kk][2] * scale, r1[kk][3] * scale);
        }
    }

    float mrow[2] = {-1e30f, -1e30f};
    float lrow[2] = {0.f, 0.f};
    float accO[16][4];
#pragma unroll
    for (int i = 0; i < 16; i++)
#pragma unroll
        for (int j = 0; j < 4; j++) accO[i][j] = 0.f;

    const int nkb = 2 * qb + 2;

    fill(0, 0);
    CP_COMMIT();

    for (int kb = 0; kb < nkb; kb++) {
        const int buf = kb & 1;
        if (kb + 1 < nkb) fill((kb + 1) & 1, kb + 1);
        CP_COMMIT();
        CP_WAIT(1);
        __syncthreads();

        const uint32_t* Ku = (const uint32_t*)(smc + buf * ATT_STAGE);
        const uint32_t* Vu = (const uint32_t*)(smc + buf * ATT_STAGE + 16384);

        float accS[8][4];
#pragma unroll
        for (int i = 0; i < 8; i++)
#pragma unroll
            for (int j = 0; j < 4; j++) accS[i][j] = 0.f;

#pragma unroll
        for (int kk = 0; kk < 8; kk++) {
            const int c0 = 2 * kk;
            const int c1 = 2 * kk + 1;
#pragma unroll
            for (int nt = 0; nt < 8; nt++) {
                const int n = nt * 8 + gID;
                uint32_t b[2];
                b[0] = Ku[n * 64 + ((c0 ^ gID) << 2) + tig];
                b[1] = Ku[n * 64 + ((c1 ^ gID) << 2) + tig];
                mma_f16(accS[nt], qf[kk], b);
            }
        }

        if (kb >= 2 * qb) {
            const int q0 = qb * BQ + wrow + gID;
            const int q1 = q0 + 8;
#pragma unroll
            for (int nt = 0; nt < 8; nt++) {
                const int kg = kb * BKV + nt * 8 + 2 * tig;
                if (kg > q0)     accS[nt][0] = -1e30f;
                if (kg + 1 > q0) accS[nt][1] = -1e30f;
                if (kg > q1)     accS[nt][2] = -1e30f;
                if (kg + 1 > q1) accS[nt][3] = -1e30f;
            }
        }

        float mx0 = -1e30f, mx1 = -1e30f;
#pragma unroll
        for (int nt = 0; nt < 8; nt++) {
            mx0 = fmaxf(mx0, fmaxf(accS[nt][0], accS[nt][1]));
            mx1 = fmaxf(mx1, fmaxf(accS[nt][2], accS[nt][3]));
        }
        mx0 = fmaxf(mx0, __shfl_xor_sync(0xffffffffu, mx0, 1));
        mx0 = fmaxf(mx0, __shfl_xor_sync(0xffffffffu, mx0, 2));
        mx1 = fmaxf(mx1, __shfl_xor_sync(0xffffffffu, mx1, 1));
        mx1 = fmaxf(mx1, __shfl_xor_sync(0xffffffffu, mx1, 2));

        float mn0 = fmaxf(mrow[0], mx0);
        float mn1 = fmaxf(mrow[1], mx1);
        float al0 = __expf(mrow[0] - mn0);
        float al1 = __expf(mrow[1] - mn1);
        mrow[0] = mn0; mrow[1] = mn1;

        float ls0 = 0.f, ls1 = 0.f;
        const int pr0 = wrow + gID;
#pragma unroll
        for (int nt = 0; nt < 8; nt++) {
            float p0 = __expf(accS[nt][0] - mn0);
            float p1 = __expf(accS[nt][1] - mn0);
            float p2 = __expf(accS[nt][2] - mn1);
            float p3 = __expf(accS[nt][3] - mn1);
            ls0 += p0 + p1;
            ls1 += p2 + p3;
            const int c = nt * 8 + 2 * tig;
            __half2 h0 = __floats2half2_rn(p0, p1);
            __half2 h1 = __floats2half2_rn(p2, p3);
            *(__half2*)(Psh + pr0 * PSH + c)       = h0;
            *(__half2*)(Psh + (pr0 + 8) * PSH + c) = h1;
        }
        ls0 += __shfl_xor_sync(0xffffffffu, ls0, 1);
        ls0 += __shfl_xor_sync(0xffffffffu, ls0, 2);
        ls1 += __shfl_xor_sync(0xffffffffu, ls1, 1);
        ls1 += __shfl_xor_sync(0xffffffffu, ls1, 2);
        lrow[0] = lrow[0] * al0 + ls0;
        lrow[1] = lrow[1] * al1 + ls1;

#pragma unroll
        for (int nt = 0; nt < 16; nt++) {
            accO[nt][0] *= al0; accO[nt][1] *= al0;
            accO[nt][2] *= al1; accO[nt][3] *= al1;
        }
        __syncwarp();

        const uint32_t* Pu = (const uint32_t*)Psh;
#pragma unroll
        for (int kk = 0; kk < 4; kk++) {
            const int c0 = 2 * kk;
            const int c1 = 2 * kk + 1;
            uint32_t a[4];
            a[0] = Pu[pr0 * (PSH / 2) + kk * 8 + tig];
            a[1] = Pu[(pr0 + 8) * (PSH / 2) + kk * 8 + tig];
            a[2] = Pu[pr0 * (PSH / 2) + kk * 8 + 4 + tig];
            a[3] = Pu[(pr0 + 8) * (PSH / 2) + kk * 8 + 4 + tig];
#pragma unroll
            for (int nt = 0; nt < 16; nt++) {
                const int n = nt * 8 + gID;
                uint32_t b[2];
                b[0] = Vu[n * 32 + ((c0 ^ gID) << 2) + tig];
                b[1] = Vu[n * 32 + ((c1 ^ gID) << 2) + tig];
                mma_f16(accO[nt], a, b);
            }
        }
        __syncthreads();
    }

    const float li0 = 1.f / lrow[0];
    const float li1 = 1.f / lrow[1];
    const int r0 = qb * BQ + wrow + gID;
    const int r1 = r0 + 8;
#pragma unroll
    for (int nt = 0; nt < 16; nt++) {
        const int c = h * HD + nt * 8 + 2 * tig;
        __half2 h0 = __floats2half2_rn(accO[nt][0] * li0, accO[nt][1] * li0);
        __half2 h1 = __floats2half2_rn(accO[nt][2] * li1, accO[nt][3] * li1);
        *(__half2*)(ctx + (size_t)r0 * DOUT + c) = h0;
        *(__half2*)(ctx + (size_t)r1 * DOUT + c) = h1;
    }
}

// ---------------------------------------------------------------------------
// Launch
// ---------------------------------------------------------------------------
extern "C" void kernel_launch(void* const* d_in, const int* in_sizes, int n_in,
                              void* d_out, int out_size)
{
    const float* x    = (const float*)d_in[0];
    const float* cosT = (const float*)d_in[1];
    const float* sinT = (const float*)d_in[2];
    const float* Wq   = (const float*)d_in[3];
    const float* Wk   = (const float*)d_in[4];
    const float* Wv   = (const float*)d_in[5];
    const float* Wo   = (const float*)d_in[6];
    float* out = (float*)d_out;

    float *Qp, *Kp, *Vp;
    __half *Kph, *Vtp, *Cph, *xh, *Wqh, *Wkh, *Wvh, *Woh;
    cudaGetSymbolAddress((void**)&Qp, g_Q);
    cudaGetSymbolAddress((void**)&Kp, g_K);
    cudaGetSymbolAddress((void**)&Vp, g_V);
    cudaGetSymbolAddress((void**)&Kph, g_Kh);
    cudaGetSymbolAddress((void**)&Vtp, g_Vth);
    cudaGetSymbolAddress((void**)&Cph, g_ctxh);
    cudaGetSymbolAddress((void**)&xh, g_xh);
    cudaGetSymbolAddress((void**)&Wqh, g_Wqh);
    cudaGetSymbolAddress((void**)&Wkh, g_Wkh);
    cudaGetSymbolAddress((void**)&Wvh, g_Wvh);
    cudaGetSymbolAddress((void**)&Woh, g_Woh);

    cudaFuncSetAttribute(gemm_qkv, cudaFuncAttributeMaxDynamicSharedMemorySize, GEMM_SMEM);
    cudaFuncSetAttribute(gemm_nt,  cudaFuncAttributeMaxDynamicSharedMemorySize, GEMM_SMEM);
    cudaFuncSetAttribute(attn_mma, cudaFuncAttributeMaxDynamicSharedMemorySize, ATT_SMEM);

    // Batched fp32 -> fp16 conversion
    round_f16_all<<<2048, 256>>>(x, Wq, Wk, Wv, Wo, xh, Wqh, Wkh, Wvh, Woh);

    // Fused QKV projection (256-row tiles)
    gemm_qkv<<<dim3(48, SEQ / 256), 256, GEMM_SMEM>>>(xh, Wqh, Wkh, Wvh, Qp, Kp, Vp);

    // K RoPE -> fp16; V transpose -> fp16
    {
        int totK = SEQ * NKV * 64;
        rope_k_h<<<(totK + 255) / 256, 256>>>(Kp, Kph, cosT, sinT);
    }
    vtrans<<<dim3(SEQ / 32, (NKV * HD) / 32), 256>>>(Vp, Vtp);

    // fp16 flash attention with fused Q-RoPE
    attn_mma<<<dim3(SEQ / BQ, NH), 256, ATT_SMEM>>>(Qp, Kph, Vtp, Cph, cosT, sinT);

    // Output projection (256-row tiles)
    gemm_nt<<<dim3(DOUT / 128, SEQ / 256), 256, GEMM_SMEM>>>(Cph, Woh, out, DIN, DOUT);
}

// round 16
// speedup vs baseline: 1.0391x; 1.0391x over previous
#include <cuda_runtime.h>
#include <cuda_fp16.h>
#include <math.h>
#include <stdint.h>

// Problem constants
#define SEQ    2048
#define DIN    4096
#define DOUT   4096
#define NH     32
#define NKV    8
#define HD     128
#define GROUP  4

// Scratch buffers
__device__ float  g_Q[SEQ * DOUT];
__device__ float  g_K[SEQ * (NKV * HD)];
__device__ __half g_Vh[SEQ * (NKV * HD)];          // fp16 V (row-major, from GEMM)
__device__ __half g_Kh[SEQ * (NKV * HD)];
__device__ __half g_Vth[(NKV * HD) * SEQ];
__device__ __half g_ctxh[SEQ * DOUT];
__device__ __half g_xh[SEQ * DIN];
__device__ __half g_Wqh[DOUT * DIN];
__device__ __half g_Wkh[(NKV * HD) * DIN];
__device__ __half g_Wvh[(NKV * HD) * DIN];
__device__ __half g_Woh[DOUT * DOUT];

// fp16 mma
__device__ __forceinline__ void mma_f16(float* c, const uint32_t* a, const uint32_t* b) {
    asm volatile(
        "mma.sync.aligned.m16n8k16.row.col.f32.f16.f16.f32 "
        "{%0,%1,%2,%3}, {%4,%5,%6,%7}, {%8,%9}, {%0,%1,%2,%3};"
        : "+f"(c[0]), "+f"(c[1]), "+f"(c[2]), "+f"(c[3])
        : "r"(a[0]), "r"(a[1]), "r"(a[2]), "r"(a[3]), "r"(b[0]), "r"(b[1]));
}

__device__ __forceinline__ void ldsm4(uint32_t* r, uint32_t addr) {
    asm volatile("ldmatrix.sync.aligned.m8n8.x4.shared.b16 {%0,%1,%2,%3}, [%4];"
        : "=r"(r[0]), "=r"(r[1]), "=r"(r[2]), "=r"(r[3]) : "r"(addr));
}

__device__ __forceinline__ uint32_t smem_u32(const void* p) {
    uint32_t a;
    asm("{ .reg .u64 t; cvta.to.shared.u64 t, %1; cvt.u32.u64 %0, t; }"
        : "=r"(a) : "l"(p));
    return a;
}

__device__ __forceinline__ void cp16(uint32_t dst, const void* src) {
    asm volatile("cp.async.cg.shared.global [%0], [%1], 16;"
                 :: "r"(dst), "l"(src) : "memory");
}
#define CP_COMMIT() asm volatile("cp.async.commit_group;" ::: "memory")
#define CP_WAIT(n)  asm volatile("cp.async.wait_group %0;" :: "n"(n) : "memory")

__device__ __forceinline__ uint32_t pack_h2(float a, float b) {
    __half2 h = __floats2half2_rn(a, b);
    return *(uint32_t*)&h;
}

// ---------------------------------------------------------------------------
// Batched fp32 -> fp16 conversion (one launch)
// ---------------------------------------------------------------------------
#define N4_X   ((SEQ * DIN) / 4)
#define N4_WQ  ((DOUT * DIN) / 4)
#define N4_WK  (((NKV * HD) * DIN) / 4)
#define N4_WV  (((NKV * HD) * DIN) / 4)
#define N4_WO  ((DOUT * DOUT) / 4)
#define N4_TOT (N4_X + N4_WQ + N4_WK + N4_WV + N4_WO)

__global__ __launch_bounds__(256) void round_f16_all(
    const float* __restrict__ x,  const float* __restrict__ Wq,
    const float* __restrict__ Wk, const float* __restrict__ Wv,
    const float* __restrict__ Wo,
    __half* __restrict__ xh,  __half* __restrict__ Wqh,
    __half* __restrict__ Wkh, __half* __restrict__ Wvh,
    __half* __restrict__ Woh)
{
    for (int i = blockIdx.x * blockDim.x + threadIdx.x; i < N4_TOT;
         i += gridDim.x * blockDim.x) {
        const float* in;
        __half* out;
        int j = i;
        if (j < N4_X)                 { in = x;  out = xh; }
        else if ((j -= N4_X)  < N4_WQ){ in = Wq; out = Wqh; }
        else if ((j -= N4_WQ) < N4_WK){ in = Wk; out = Wkh; }
        else if ((j -= N4_WK) < N4_WV){ in = Wv; out = Wvh; }
        else { j -= N4_WV;              in = Wo; out = Woh; }
        float4 v = *(const float4*)(in + (size_t)j * 4);
        __half2 h0 = __floats2half2_rn(v.x, v.y);
        __half2 h1 = __floats2half2_rn(v.z, v.w);
        *(uint2*)(out + (size_t)j * 4) =
            make_uint2(*(uint32_t*)&h0, *(uint32_t*)&h1);
    }
}

// ---------------------------------------------------------------------------
// Merged K-RoPE (fp32->fp16) + V transpose (fp16->fp16), one launch.
// Blocks [0, KB_ROPE): rope on K. Blocks [KB_ROPE, ...): 32x32 V transpose.
// ---------------------------------------------------------------------------
#define KB_ROPE ((SEQ * NKV * 64 + 255) / 256)
#define KB_VT_X (SEQ / 32)
#define KB_VT_Y ((NKV * HD) / 32)

__global__ __launch_bounds__(256) void ropek_vtrans(
    const float* __restrict__ K, __half* __restrict__ Kh,
    const __half* __restrict__ Vhrow, __half* __restrict__ Vt,
    const float* __restrict__ cosT, const float* __restrict__ sinT)
{
    if (blockIdx.x < KB_ROPE) {
        int idx = blockIdx.x * 256 + threadIdx.x;
        int total = SEQ * NKV * 64;
        if (idx >= total) return;
        int d = idx & 63;
        int h = (idx >> 6) % NKV;
        int s = idx / (64 * NKV);
        const float* row = K + (size_t)s * (NKV * HD) + h * HD;
        __half* rowh = Kh + (size_t)s * (NKV * HD) + h * HD;
        float x1 = row[d];
        float x2 = row[d + 64];
        rowh[d]      = __float2half_rn(fmaf(x1, cosT[s * HD + d],      -x2 * sinT[s * HD + d]));
        rowh[d + 64] = __float2half_rn(fmaf(x2, cosT[s * HD + d + 64],  x1 * sinT[s * HD + d + 64]));
    } else {
        __shared__ __half t[32][40];
        const int b = blockIdx.x - KB_ROPE;
        const int s0 = (b % KB_VT_X) * 32;
        const int c0 = (b / KB_VT_X) * 32;
        const int tx = threadIdx.x & 31;
        const int ty = threadIdx.x >> 5;
#pragma unroll
        for (int i = ty; i < 32; i += 8)
            t[i][tx] = Vhrow[(size_t)(s0 + i) * (NKV * HD) + c0 + tx];
        __syncthreads();
#pragma unroll
        for (int i = ty; i < 32; i += 8)
            Vt[(size_t)(c0 + i) * SEQ + s0 + tx] = t[tx][i];
    }
}

// ===========================================================================
// fp16 GEMM core (Round 13/14 — validated). Optional fp16 output (for V).
// ===========================================================================
#define GS 3
#define STAGE_BYTES 32768
#define GEMM_SMEM (GS * STAGE_BYTES)

__device__ __forceinline__ void gemm_core_h(
    const __half* __restrict__ A, const __half* __restrict__ B,
    float* __restrict__ C, __half* __restrict__ Ch, int K, int ldc, int bm)
{
    extern __shared__ char sbuf[];
    const uint32_t sbase = smem_u32(sbuf);
    const int tid  = threadIdx.x;
    const int lane = tid & 31;
    const int warp = tid >> 5;
    const int gID  = lane >> 2;
    const int tig  = lane & 3;
    const int wm   = (warp & 1) * 64;
    const int wn   = (warp >> 1) * 64;

    const int fr = tid >> 3;
    const int fc = tid & 7;

    const int l7    = lane & 7;
    const int aRowL = l7 + ((lane >> 3) & 1) * 8;
    const int aChO  = lane >> 4;
    const int bRowL = l7 + (lane >> 4) * 8;
    const int bChO  = (lane >> 3) & 1;

    float acc[4][8][4];
#pragma unroll
    for (int mi = 0; mi < 4; mi++)
#pragma unroll
        for (int ni = 0; ni < 8; ni++)
#pragma unroll
            for (int j = 0; j < 4; j++) acc[mi][ni][j] = 0.f;

    const int nK = K >> 6;

    auto fill = [&](int st, int kt) {
        const uint32_t dA = sbase + st * STAGE_BYTES;
        const uint32_t dB = dA + 16384;
        const __half* gA = A + (size_t)bm * K + kt * 64;
        const __half* gB = B + (size_t)kt * 64;
#pragma unroll
        for (int i = 0; i < 8; i++) {
            const int r = fr + i * 16;
            const uint32_t sw = (uint32_t)(r * 128 + ((fc ^ (r & 7)) * 16));
            cp16(dA + sw, gA + (size_t)r * K + fc * 8);
            cp16(dB + sw, gB + (size_t)r * K + fc * 8);
        }
    };

#pragma unroll
    for (int s = 0; s < GS - 1; s++) {
        if (s < nK) fill(s, s);
        CP_COMMIT();
    }

    for (int kt = 0; kt < nK; kt++) {
        const int nxt = kt + GS - 1;
        if (nxt < nK) fill(nxt % GS, nxt);
        CP_COMMIT();
        CP_WAIT(2);
        __syncthreads();

        const uint32_t sa = sbase + (kt % GS) * STAGE_BYTES;
        const uint32_t sb = sa + 16384;
        uint32_t aBase[4], bBase[4];
#pragma unroll
        for (int mi = 0; mi < 4; mi++)
            aBase[mi] = sa + (uint32_t)((wm + mi * 16 + aRowL) * 128);
#pragma unroll
        for (int nj = 0; nj < 4; nj++)
            bBase[nj] = sb + (uint32_t)((wn + nj * 16 + bRowL) * 128);

#pragma unroll
        for (int kk = 0; kk < 4; kk++) {
            const int chA = 2 * kk + aChO;
            const int chB = 2 * kk + bChO;
            const uint32_t swA = (uint32_t)((chA ^ l7) << 4);
            const uint32_t swB = (uint32_t)((chB ^ l7) << 4);

            uint32_t af[4][4], bf[8][2];
#pragma unroll
            for (int mi = 0; mi < 4; mi++)
                ldsm4(af[mi], aBase[mi] + swA);
#pragma unroll
            for (int nj = 0; nj < 4; nj++) {
                uint32_t tmp[4];
                ldsm4(tmp, bBase[nj] + swB);
                bf[2 * nj][0]     = tmp[0];
                bf[2 * nj][1]     = tmp[1];
                bf[2 * nj + 1][0] = tmp[2];
                bf[2 * nj + 1][1] = tmp[3];
            }
#pragma unroll
            for (int mi = 0; mi < 4; mi++)
#pragma unroll
                for (int ni = 0; ni < 8; ni++)
                    mma_f16(acc[mi][ni], af[mi], bf[ni]);
        }
        __syncthreads();
    }

    if (Ch) {
        // fp16 output (V path): same single rounding vtrans used to apply
#pragma unroll
        for (int mi = 0; mi < 4; mi++) {
            const int r0 = bm + wm + mi * 16 + gID;
#pragma unroll
            for (int ni = 0; ni < 8; ni++) {
                const int c0 = wn + ni * 8 + tig * 2;
                const float* c = acc[mi][ni];
                __half2 h0 = __floats2half2_rn(c[0], c[1]);
                __half2 h1 = __floats2half2_rn(c[2], c[3]);
                *(__half2*)(Ch + (size_t)r0 * ldc + c0)       = h0;
                *(__half2*)(Ch + (size_t)(r0 + 8) * ldc + c0) = h1;
            }
        }
    } else {
#pragma unroll
        for (int mi = 0; mi < 4; mi++) {
            const int r0 = bm + wm + mi * 16 + gID;
#pragma unroll
            for (int ni = 0; ni < 8; ni++) {
                const int c0 = wn + ni * 8 + tig * 2;
                const float* c = acc[mi][ni];
                *(float2*)(C + (size_t)r0 * ldc + c0)       = make_float2(c[0], c[1]);
                *(float2*)(C + (size_t)(r0 + 8) * ldc + c0) = make_float2(c[2], c[3]);
            }
        }
    }
}

__global__ __launch_bounds__(128, 2) void gemm_qkv(
    const __half* __restrict__ x,
    const __half* __restrict__ Wq, const __half* __restrict__ Wk,
    const __half* __restrict__ Wv,
    float* __restrict__ Q, float* __restrict__ Ko, __half* __restrict__ Vo)
{
    const int bn = blockIdx.x;
    const int bm = blockIdx.y * 128;
    if (bn < 32) {
        gemm_core_h(x, Wq + (size_t)bn * 128 * DIN, Q + bn * 128, nullptr,
                    DIN, DOUT, bm);
    } else if (bn < 40) {
        const int coff = (bn - 32) * 128;
        gemm_core_h(x, Wk + (size_t)coff * DIN, Ko + coff, nullptr,
                    DIN, NKV * HD, bm);
    } else {
        const int coff = (bn - 40) * 128;
        gemm_core_h(x, Wv + (size_t)coff * DIN, nullptr, Vo + coff,
                    DIN, NKV * HD, bm);
    }
}

__global__ __launch_bounds__(128, 2) void gemm_nt(
    const __half* __restrict__ A, const __half* __restrict__ B,
    float* __restrict__ C, int K, int N)
{
    const int coff = blockIdx.x * 128;
    gemm_core_h(A, B + (size_t)coff * K, C + coff, nullptr, K, N, blockIdx.y * 128);
}

// ---------------------------------------------------------------------------
// fp16 flash attention, fused Q-RoPE (R14), single barrier per tile (R16).
// ---------------------------------------------------------------------------
#define BQ   128
#define BKV  64
#define PSH  72
#define ATT_STAGE 32768
#define ATT_SMEM  (2 * ATT_STAGE + BQ * PSH * 2)

__global__ __launch_bounds__(256, 1) void attn_mma(
    const float* __restrict__ Q, const __half* __restrict__ Kh,
    const __half* __restrict__ Vt, __half* __restrict__ ctx,
    const float* __restrict__ cosT, const float* __restrict__ sinT)
{
    const int qb  = gridDim.x - 1 - blockIdx.x;
    const int h   = blockIdx.y;
    const int hk  = h >> 2;
    const int tid = threadIdx.x;
    const int lane = tid & 31;
    const int warp = tid >> 5;
    const int gID  = lane >> 2;
    const int tig  = lane & 3;
    const int wrow = warp * 16;

    extern __shared__ char smc[];
    const uint32_t sbase = smem_u32(smc);
    __half* Psh = (__half*)(smc + 2 * ATT_STAGE);

    const float scale = 0.08838834764831845f;

    auto fill = [&](int buf, int kb) {
        {
            const int r  = tid >> 2;
            const uint32_t kdst = sbase + buf * ATT_STAGE + r * 256;
            const __half* ksrc = Kh + (size_t)(kb * BKV + r) * (NKV * HD) + hk * HD;
#pragma unroll
            for (int j = 0; j < 4; j++) {
                const int ch = (tid & 3) * 4 + j;
                cp16(kdst + (uint32_t)((ch ^ (r & 7)) << 4), ksrc + ch * 8);
            }
        }
        {
            const int r  = tid >> 1;
            const uint32_t vdst = sbase + buf * ATT_STAGE + 16384 + r * 128;
            const __half* vsrc = Vt + (size_t)(hk * HD + r) * SEQ + kb * BKV;
#pragma unroll
            for (int j = 0; j < 4; j++) {
                const int ch = (tid & 1) * 4 + j;
                cp16(vdst + (uint32_t)((ch ^ (r & 7)) << 4), vsrc + ch * 8);
            }
        }
    };

    // ---- Q fragments: load raw, RoPE in registers, pack fp16 ----
    uint32_t qf[8][4];
    {
        const int s0 = qb * BQ + wrow + gID;
        const int s1 = s0 + 8;
        const float* q0 = Q + (size_t)s0 * DOUT + h * HD;
        const float* q1 = Q + (size_t)s1 * DOUT + h * HD;

        float r0[8][4], r1[8][4];
#pragma unroll
        for (int kk = 0; kk < 8; kk++) {
            const int k = kk * 16;
            r0[kk][0] = q0[k + 2 * tig];     r0[kk][1] = q0[k + 2 * tig + 1];
            r0[kk][2] = q0[k + 8 + 2 * tig]; r0[kk][3] = q0[k + 9 + 2 * tig];
            r1[kk][0] = q1[k + 2 * tig];     r1[kk][1] = q1[k + 2 * tig + 1];
            r1[kk][2] = q1[k + 8 + 2 * tig]; r1[kk][3] = q1[k + 9 + 2 * tig];
        }
        const int off[4] = {2 * tig, 2 * tig + 1, 8 + 2 * tig, 9 + 2 * tig};
#pragma unroll
        for (int kk = 0; kk < 4; kk++) {
#pragma unroll
            for (int j = 0; j < 4; j++) {
                const int d = kk * 16 + off[j];
                const float cL  = cosT[s0 * HD + d],      sL  = sinT[s0 * HD + d];
                const float cH  = cosT[s0 * HD + d + 64], sH  = sinT[s0 * HD + d + 64];
                const float cL1 = cosT[s1 * HD + d],      sL1 = sinT[s1 * HD + d];
                const float cH1 = cosT[s1 * HD + d + 64], sH1 = sinT[s1 * HD + d + 64];
                float lo, hi;
                lo = r0[kk][j]; hi = r0[kk + 4][j];
                r0[kk][j]     = fmaf(lo, cL, -hi * sL);
                r0[kk + 4][j] = fmaf(hi, cH,  lo * sH);
                lo = r1[kk][j]; hi = r1[kk + 4][j];
                r1[kk][j]     = fmaf(lo, cL1, -hi * sL1);
                r1[kk + 4][j] = fmaf(hi, cH1,  lo * sH1);
            }
        }
#pragma unroll
        for (int kk = 0; kk < 8; kk++) {
            qf[kk][0] = pack_h2(r0[kk][0] * scale, r0[kk][1] * scale);
            qf[kk][1] = pack_h2(r1[kk][0] * scale, r1[kk][1] * scale);
            qf[kk][2] = pack_h2(r0[kk][2] * scale, r0[kk][3] * scale);
            qf[kk][3] = pack_h2(r1[kk][2] * scale, r1[kk][3] * scale);
        }
    }

    float mrow[2] = {-1e30f, -1e30f};
    float lrow[2] = {0.f, 0.f};
    float accO[16][4];
#pragma unroll
    for (int i = 0; i < 16; i++)
#pragma unroll
        for (int j = 0; j < 4; j++) accO[i][j] = 0.f;

    const int nkb = 2 * qb + 2;

    fill(0, 0);
    CP_COMMIT();

    for (int kb = 0; kb < nkb; kb++) {
        const int buf = kb & 1;
        // single barrier per tile: wait for this tile's fill, sync orders
        // previous compute before the next fill overwrites its buffer.
        CP_WAIT(0);
        __syncthreads();
        if (kb + 1 < nkb) fill((kb + 1) & 1, kb + 1);
        CP_COMMIT();

        const uint32_t* Ku = (const uint32_t*)(smc + buf * ATT_STAGE);
        const uint32_t* Vu = (const uint32_t*)(smc + buf * ATT_STAGE + 16384);

        float accS[8][4];
#pragma unroll
        for (int i = 0; i < 8; i++)
#pragma unroll
            for (int j = 0; j < 4; j++) accS[i][j] = 0.f;

#pragma unroll
        for (int kk = 0; kk < 8; kk++) {
            const int c0 = 2 * kk;
            const int c1 = 2 * kk + 1;
#pragma unroll
            for (int nt = 0; nt < 8; nt++) {
                const int n = nt * 8 + gID;
                uint32_t b[2];
                b[0] = Ku[n * 64 + ((c0 ^ gID) << 2) + tig];
                b[1] = Ku[n * 64 + ((c1 ^ gID) << 2) + tig];
                mma_f16(accS[nt], qf[kk], b);
            }
        }

        if (kb >= 2 * qb) {
            const int q0 = qb * BQ + wrow + gID;
            const int q1 = q0 + 8;
#pragma unroll
            for (int nt = 0; nt < 8; nt++) {
                const int kg = kb * BKV + nt * 8 + 2 * tig;
                if (kg > q0)     accS[nt][0] = -1e30f;
                if (kg + 1 > q0) accS[nt][1] = -1e30f;
                if (kg > q1)     accS[nt][2] = -1e30f;
                if (kg + 1 > q1) accS[nt][3] = -1e30f;
            }
        }

        float mx0 = -1e30f, mx1 = -1e30f;
#pragma unroll
        for (int nt = 0; nt < 8; nt++) {
            mx0 = fmaxf(mx0, fmaxf(accS[nt][0], accS[nt][1]));
            mx1 = fmaxf(mx1, fmaxf(accS[nt][2], accS[nt][3]));
        }
        mx0 = fmaxf(mx0, __shfl_xor_sync(0xffffffffu, mx0, 1));
        mx0 = fmaxf(mx0, __shfl_xor_sync(0xffffffffu, mx0, 2));
        mx1 = fmaxf(mx1, __shfl_xor_sync(0xffffffffu, mx1, 1));
        mx1 = fmaxf(mx1, __shfl_xor_sync(0xffffffffu, mx1, 2));

        float mn0 = fmaxf(mrow[0], mx0);
        float mn1 = fmaxf(mrow[1], mx1);
        float al0 = __expf(mrow[0] - mn0);
        float al1 = __expf(mrow[1] - mn1);
        mrow[0] = mn0; mrow[1] = mn1;

        float ls0 = 0.f, ls1 = 0.f;
        const int pr0 = wrow + gID;
#pragma unroll
        for (int nt = 0; nt < 8; nt++) {
            float p0 = __expf(accS[nt][0] - mn0);
            float p1 = __expf(accS[nt][1] - mn0);
            float p2 = __expf(accS[nt][2] - mn1);
            float p3 = __expf(accS[nt][3] - mn1);
            ls0 += p0 + p1;
            ls1 += p2 + p3;
            const int c = nt * 8 + 2 * tig;
            __half2 h0 = __floats2half2_rn(p0, p1);
            __half2 h1 = __floats2half2_rn(p2, p3);
            *(__half2*)(Psh + pr0 * PSH + c)       = h0;
            *(__half2*)(Psh + (pr0 + 8) * PSH + c) = h1;
        }
        ls0 += __shfl_xor_sync(0xffffffffu, ls0, 1);
        ls0 += __shfl_xor_sync(0xffffffffu, ls0, 2);
        ls1 += __shfl_xor_sync(0xffffffffu, ls1, 1);
        ls1 += __shfl_xor_sync(0xffffffffu, ls1, 2);
        lrow[0] = lrow[0] * al0 + ls0;
        lrow[1] = lrow[1] * al1 + ls1;

#pragma unroll
        for (int nt = 0; nt < 16; nt++) {
            accO[nt][0] *= al0; accO[nt][1] *= al0;
            accO[nt][2] *= al1; accO[nt][3] *= al1;
        }
        __syncwarp();

        const uint32_t* Pu = (const uint32_t*)Psh;
#pragma unroll
        for (int kk = 0; kk < 4; kk++) {
            const int c0 = 2 * kk;
            const int c1 = 2 * kk + 1;
            uint32_t a[4];
            a[0] = Pu[pr0 * (PSH / 2) + kk * 8 + tig];
            a[1] = Pu[(pr0 + 8) * (PSH / 2) + kk * 8 + tig];
            a[2] = Pu[pr0 * (PSH / 2) + kk * 8 + 4 + tig];
            a[3] = Pu[(pr0 + 8) * (PSH / 2) + kk * 8 + 4 + tig];
#pragma unroll
            for (int nt = 0; nt < 16; nt++) {
                const int n = nt * 8 + gID;
                uint32_t b[2];
                b[0] = Vu[n * 32 + ((c0 ^ gID) << 2) + tig];
                b[1] = Vu[n * 32 + ((c1 ^ gID) << 2) + tig];
                mma_f16(accO[nt], a, b);
            }
        }
    }

    const float li0 = 1.f / lrow[0];
    const float li1 = 1.f / lrow[1];
    const int r0 = qb * BQ + wrow + gID;
    const int r1 = r0 + 8;
#pragma unroll
    for (int nt = 0; nt < 16; nt++) {
        const int c = h * HD + nt * 8 + 2 * tig;
        __half2 h0 = __floats2half2_rn(accO[nt][0] * li0, accO[nt][1] * li0);
        __half2 h1 = __floats2half2_rn(accO[nt][2] * li1, accO[nt][3] * li1);
        *(__half2*)(ctx + (size_t)r0 * DOUT + c) = h0;
        *(__half2*)(ctx + (size_t)r1 * DOUT + c) = h1;
    }
}

// ---------------------------------------------------------------------------
// Launch
// ---------------------------------------------------------------------------
extern "C" void kernel_launch(void* const* d_in, const int* in_sizes, int n_in,
                              void* d_out, int out_size)
{
    const float* x    = (const float*)d_in[0];
    const float* cosT = (const float*)d_in[1];
    const float* sinT = (const float*)d_in[2];
    const float* Wq   = (const float*)d_in[3];
    const float* Wk   = (const float*)d_in[4];
    const float* Wv   = (const float*)d_in[5];
    const float* Wo   = (const float*)d_in[6];
    float* out = (float*)d_out;

    float *Qp, *Kp;
    __half *Vhp, *Kph, *Vtp, *Cph, *xh, *Wqh, *Wkh, *Wvh, *Woh;
    cudaGetSymbolAddress((void**)&Qp, g_Q);
    cudaGetSymbolAddress((void**)&Kp, g_K);
    cudaGetSymbolAddress((void**)&Vhp, g_Vh);
    cudaGetSymbolAddress((void**)&Kph, g_Kh);
    cudaGetSymbolAddress((void**)&Vtp, g_Vth);
    cudaGetSymbolAddress((void**)&Cph, g_ctxh);
    cudaGetSymbolAddress((void**)&xh, g_xh);
    cudaGetSymbolAddress((void**)&Wqh, g_Wqh);
    cudaGetSymbolAddress((void**)&Wkh, g_Wkh);
    cudaGetSymbolAddress((void**)&Wvh, g_Wvh);
    cudaGetSymbolAddress((void**)&Woh, g_Woh);

    cudaFuncSetAttribute(gemm_qkv, cudaFuncAttributeMaxDynamicSharedMemorySize, GEMM_SMEM);
    cudaFuncSetAttribute(gemm_nt,  cudaFuncAttributeMaxDynamicSharedMemorySize, GEMM_SMEM);
    cudaFuncSetAttribute(attn_mma, cudaFuncAttributeMaxDynamicSharedMemorySize, ATT_SMEM);

    // Batched fp32 -> fp16 conversion
    round_f16_all<<<2048, 256>>>(x, Wq, Wk, Wv, Wo, xh, Wqh, Wkh, Wvh, Woh);

    // Fused QKV projection (V written fp16 directly)
    gemm_qkv<<<dim3(48, SEQ / 128), 128, GEMM_SMEM>>>(xh, Wqh, Wkh, Wvh, Qp, Kp, Vhp);

    // Merged K-RoPE + V-transpose (one launch)
    ropek_vtrans<<<KB_ROPE + KB_VT_X * KB_VT_Y, 256>>>(Kp, Kph, Vhp, Vtp, cosT, sinT);

    // fp16 flash attention with fused Q-RoPE
    attn_mma<<<dim3(SEQ / BQ, NH), 256, ATT_SMEM>>>(Qp, Kph, Vtp, Cph, cosT, sinT);

    // Output projection
    gemm_nt<<<dim3(DOUT / 128, SEQ / 128), 128, GEMM_SMEM>>>(Cph, Woh, out, DIN, DOUT);
}

// round 17
// speedup vs baseline: 1.0569x; 1.0171x over previous
#include <cuda_runtime.h>
#include <cuda_fp16.h>
#include <math.h>
#include <stdint.h>

// Problem constants
#define SEQ    2048
#define DIN    4096
#define DOUT   4096
#define NH     32
#define NKV    8
#define HD     128
#define GROUP  4

// Scratch buffers
__device__ float  g_Q[SEQ * DOUT];
__device__ float  g_K[SEQ * (NKV * HD)];
__device__ __half g_Vh[SEQ * (NKV * HD)];
__device__ __half g_Kh[SEQ * (NKV * HD)];
__device__ __half g_Vth[(NKV * HD) * SEQ];
__device__ __half g_ctxh[SEQ * DOUT];
__device__ __half g_xh[SEQ * DIN];
__device__ __half g_Wqh[DOUT * DIN];
__device__ __half g_Wkh[(NKV * HD) * DIN];
__device__ __half g_Wvh[(NKV * HD) * DIN];
__device__ __half g_Woh[DOUT * DOUT];

// fp16 mma
__device__ __forceinline__ void mma_f16(float* c, const uint32_t* a, const uint32_t* b) {
    asm volatile(
        "mma.sync.aligned.m16n8k16.row.col.f32.f16.f16.f32 "
        "{%0,%1,%2,%3}, {%4,%5,%6,%7}, {%8,%9}, {%0,%1,%2,%3};"
        : "+f"(c[0]), "+f"(c[1]), "+f"(c[2]), "+f"(c[3])
        : "r"(a[0]), "r"(a[1]), "r"(a[2]), "r"(a[3]), "r"(b[0]), "r"(b[1]));
}

__device__ __forceinline__ void ldsm4(uint32_t* r, uint32_t addr) {
    asm volatile("ldmatrix.sync.aligned.m8n8.x4.shared.b16 {%0,%1,%2,%3}, [%4];"
        : "=r"(r[0]), "=r"(r[1]), "=r"(r[2]), "=r"(r[3]) : "r"(addr));
}

__device__ __forceinline__ uint32_t smem_u32(const void* p) {
    uint32_t a;
    asm("{ .reg .u64 t; cvta.to.shared.u64 t, %1; cvt.u32.u64 %0, t; }"
        : "=r"(a) : "l"(p));
    return a;
}

__device__ __forceinline__ void cp16(uint32_t dst, const void* src) {
    asm volatile("cp.async.cg.shared.global [%0], [%1], 16;"
                 :: "r"(dst), "l"(src) : "memory");
}
#define CP_COMMIT() asm volatile("cp.async.commit_group;" ::: "memory")
#define CP_WAIT(n)  asm volatile("cp.async.wait_group %0;" :: "n"(n) : "memory")

__device__ __forceinline__ uint32_t pack_h2(float a, float b) {
    __half2 h = __floats2half2_rn(a, b);
    return *(uint32_t*)&h;
}

// ---------------------------------------------------------------------------
// Batched fp32 -> fp16 conversion (one launch)
// ---------------------------------------------------------------------------
#define N4_X   ((SEQ * DIN) / 4)
#define N4_WQ  ((DOUT * DIN) / 4)
#define N4_WK  (((NKV * HD) * DIN) / 4)
#define N4_WV  (((NKV * HD) * DIN) / 4)
#define N4_WO  ((DOUT * DOUT) / 4)
#define N4_TOT (N4_X + N4_WQ + N4_WK + N4_WV + N4_WO)

__global__ __launch_bounds__(256) void round_f16_all(
    const float* __restrict__ x,  const float* __restrict__ Wq,
    const float* __restrict__ Wk, const float* __restrict__ Wv,
    const float* __restrict__ Wo,
    __half* __restrict__ xh,  __half* __restrict__ Wqh,
    __half* __restrict__ Wkh, __half* __restrict__ Wvh,
    __half* __restrict__ Woh)
{
    for (int i = blockIdx.x * blockDim.x + threadIdx.x; i < N4_TOT;
         i += gridDim.x * blockDim.x) {
        const float* in;
        __half* out;
        int j = i;
        if (j < N4_X)                 { in = x;  out = xh; }
        else if ((j -= N4_X)  < N4_WQ){ in = Wq; out = Wqh; }
        else if ((j -= N4_WQ) < N4_WK){ in = Wk; out = Wkh; }
        else if ((j -= N4_WK) < N4_WV){ in = Wv; out = Wvh; }
        else { j -= N4_WV;              in = Wo; out = Woh; }
        float4 v = *(const float4*)(in + (size_t)j * 4);
        __half2 h0 = __floats2half2_rn(v.x, v.y);
        __half2 h1 = __floats2half2_rn(v.z, v.w);
        *(uint2*)(out + (size_t)j * 4) =
            make_uint2(*(uint32_t*)&h0, *(uint32_t*)&h1);
    }
}

// ---------------------------------------------------------------------------
// Merged K-RoPE (fp32->fp16) + V transpose (fp16->fp16)
// ---------------------------------------------------------------------------
#define KB_ROPE ((SEQ * NKV * 64 + 255) / 256)
#define KB_VT_X (SEQ / 32)
#define KB_VT_Y ((NKV * HD) / 32)

__global__ __launch_bounds__(256) void ropek_vtrans(
    const float* __restrict__ K, __half* __restrict__ Kh,
    const __half* __restrict__ Vhrow, __half* __restrict__ Vt,
    const float* __restrict__ cosT, const float* __restrict__ sinT)
{
    if (blockIdx.x < KB_ROPE) {
        int idx = blockIdx.x * 256 + threadIdx.x;
        int total = SEQ * NKV * 64;
        if (idx >= total) return;
        int d = idx & 63;
        int h = (idx >> 6) % NKV;
        int s = idx / (64 * NKV);
        const float* row = K + (size_t)s * (NKV * HD) + h * HD;
        __half* rowh = Kh + (size_t)s * (NKV * HD) + h * HD;
        float x1 = row[d];
        float x2 = row[d + 64];
        rowh[d]      = __float2half_rn(fmaf(x1, cosT[s * HD + d],      -x2 * sinT[s * HD + d]));
        rowh[d + 64] = __float2half_rn(fmaf(x2, cosT[s * HD + d + 64],  x1 * sinT[s * HD + d + 64]));
    } else {
        __shared__ __half t[32][40];
        const int b = blockIdx.x - KB_ROPE;
        const int s0 = (b % KB_VT_X) * 32;
        const int c0 = (b / KB_VT_X) * 32;
        const int tx = threadIdx.x & 31;
        const int ty = threadIdx.x >> 5;
#pragma unroll
        for (int i = ty; i < 32; i += 8)
            t[i][tx] = Vhrow[(size_t)(s0 + i) * (NKV * HD) + c0 + tx];
        __syncthreads();
#pragma unroll
        for (int i = ty; i < 32; i += 8)
            Vt[(size_t)(c0 + i) * SEQ + s0 + tx] = t[tx][i];
    }
}

// ===========================================================================
// fp16 GEMM core (Round 13/14 — validated). Optional fp16 output (for V).
// ===========================================================================
#define GS 3
#define STAGE_BYTES 32768
#define GEMM_SMEM (GS * STAGE_BYTES)

__device__ __forceinline__ void gemm_core_h(
    const __half* __restrict__ A, const __half* __restrict__ B,
    float* __restrict__ C, __half* __restrict__ Ch, int K, int ldc, int bm)
{
    extern __shared__ char sbuf[];
    const uint32_t sbase = smem_u32(sbuf);
    const int tid  = threadIdx.x;
    const int lane = tid & 31;
    const int warp = tid >> 5;
    const int gID  = lane >> 2;
    const int tig  = lane & 3;
    const int wm   = (warp & 1) * 64;
    const int wn   = (warp >> 1) * 64;

    const int fr = tid >> 3;
    const int fc = tid & 7;

    const int l7    = lane & 7;
    const int aRowL = l7 + ((lane >> 3) & 1) * 8;
    const int aChO  = lane >> 4;
    const int bRowL = l7 + (lane >> 4) * 8;
    const int bChO  = (lane >> 3) & 1;

    float acc[4][8][4];
#pragma unroll
    for (int mi = 0; mi < 4; mi++)
#pragma unroll
        for (int ni = 0; ni < 8; ni++)
#pragma unroll
            for (int j = 0; j < 4; j++) acc[mi][ni][j] = 0.f;

    const int nK = K >> 6;

    auto fill = [&](int st, int kt) {
        const uint32_t dA = sbase + st * STAGE_BYTES;
        const uint32_t dB = dA + 16384;
        const __half* gA = A + (size_t)bm * K + kt * 64;
        const __half* gB = B + (size_t)kt * 64;
#pragma unroll
        for (int i = 0; i < 8; i++) {
            const int r = fr + i * 16;
            const uint32_t sw = (uint32_t)(r * 128 + ((fc ^ (r & 7)) * 16));
            cp16(dA + sw, gA + (size_t)r * K + fc * 8);
            cp16(dB + sw, gB + (size_t)r * K + fc * 8);
        }
    };

#pragma unroll
    for (int s = 0; s < GS - 1; s++) {
        if (s < nK) fill(s, s);
        CP_COMMIT();
    }

    for (int kt = 0; kt < nK; kt++) {
        const int nxt = kt + GS - 1;
        if (nxt < nK) fill(nxt % GS, nxt);
        CP_COMMIT();
        CP_WAIT(2);
        __syncthreads();

        const uint32_t sa = sbase + (kt % GS) * STAGE_BYTES;
        const uint32_t sb = sa + 16384;
        uint32_t aBase[4], bBase[4];
#pragma unroll
        for (int mi = 0; mi < 4; mi++)
            aBase[mi] = sa + (uint32_t)((wm + mi * 16 + aRowL) * 128);
#pragma unroll
        for (int nj = 0; nj < 4; nj++)
            bBase[nj] = sb + (uint32_t)((wn + nj * 16 + bRowL) * 128);

#pragma unroll
        for (int kk = 0; kk < 4; kk++) {
            const int chA = 2 * kk + aChO;
            const int chB = 2 * kk + bChO;
            const uint32_t swA = (uint32_t)((chA ^ l7) << 4);
            const uint32_t swB = (uint32_t)((chB ^ l7) << 4);

            uint32_t af[4][4], bf[8][2];
#pragma unroll
            for (int mi = 0; mi < 4; mi++)
                ldsm4(af[mi], aBase[mi] + swA);
#pragma unroll
            for (int nj = 0; nj < 4; nj++) {
                uint32_t tmp[4];
                ldsm4(tmp, bBase[nj] + swB);
                bf[2 * nj][0]     = tmp[0];
                bf[2 * nj][1]     = tmp[1];
                bf[2 * nj + 1][0] = tmp[2];
                bf[2 * nj + 1][1] = tmp[3];
            }
#pragma unroll
            for (int mi = 0; mi < 4; mi++)
#pragma unroll
                for (int ni = 0; ni < 8; ni++)
                    mma_f16(acc[mi][ni], af[mi], bf[ni]);
        }
        __syncthreads();
    }

    if (Ch) {
#pragma unroll
        for (int mi = 0; mi < 4; mi++) {
            const int r0 = bm + wm + mi * 16 + gID;
#pragma unroll
            for (int ni = 0; ni < 8; ni++) {
                const int c0 = wn + ni * 8 + tig * 2;
                const float* c = acc[mi][ni];
                __half2 h0 = __floats2half2_rn(c[0], c[1]);
                __half2 h1 = __floats2half2_rn(c[2], c[3]);
                *(__half2*)(Ch + (size_t)r0 * ldc + c0)       = h0;
                *(__half2*)(Ch + (size_t)(r0 + 8) * ldc + c0) = h1;
            }
        }
    } else {
#pragma unroll
        for (int mi = 0; mi < 4; mi++) {
            const int r0 = bm + wm + mi * 16 + gID;
#pragma unroll
            for (int ni = 0; ni < 8; ni++) {
                const int c0 = wn + ni * 8 + tig * 2;
                const float* c = acc[mi][ni];
                *(float2*)(C + (size_t)r0 * ldc + c0)       = make_float2(c[0], c[1]);
                *(float2*)(C + (size_t)(r0 + 8) * ldc + c0) = make_float2(c[2], c[3]);
            }
        }
    }
}

__global__ __launch_bounds__(128, 2) void gemm_qkv(
    const __half* __restrict__ x,
    const __half* __restrict__ Wq, const __half* __restrict__ Wk,
    const __half* __restrict__ Wv,
    float* __restrict__ Q, float* __restrict__ Ko, __half* __restrict__ Vo)
{
    const int bn = blockIdx.x;
    const int bm = blockIdx.y * 128;
    if (bn < 32) {
        gemm_core_h(x, Wq + (size_t)bn * 128 * DIN, Q + bn * 128, nullptr,
                    DIN, DOUT, bm);
    } else if (bn < 40) {
        const int coff = (bn - 32) * 128;
        gemm_core_h(x, Wk + (size_t)coff * DIN, Ko + coff, nullptr,
                    DIN, NKV * HD, bm);
    } else {
        const int coff = (bn - 40) * 128;
        gemm_core_h(x, Wv + (size_t)coff * DIN, nullptr, Vo + coff,
                    DIN, NKV * HD, bm);
    }
}

__global__ __launch_bounds__(128, 2) void gemm_nt(
    const __half* __restrict__ A, const __half* __restrict__ B,
    float* __restrict__ C, int K, int N)
{
    const int coff = blockIdx.x * 128;
    gemm_core_h(A, B + (size_t)coff * K, C + coff, nullptr, K, N, blockIdx.y * 128);
}

// ---------------------------------------------------------------------------
// fp16 flash attention: fused Q-RoPE (R14), single barrier (R16),
// ldmatrix fragment loads (R17).
// ---------------------------------------------------------------------------
#define BQ   128
#define BKV  64
#define PSH  72
#define ATT_STAGE 32768
#define ATT_SMEM  (2 * ATT_STAGE + BQ * PSH * 2)

__global__ __launch_bounds__(256, 1) void attn_mma(
    const float* __restrict__ Q, const __half* __restrict__ Kh,
    const __half* __restrict__ Vt, __half* __restrict__ ctx,
    const float* __restrict__ cosT, const float* __restrict__ sinT)
{
    const int qb  = gridDim.x - 1 - blockIdx.x;
    const int h   = blockIdx.y;
    const int hk  = h >> 2;
    const int tid = threadIdx.x;
    const int lane = tid & 31;
    const int warp = tid >> 5;
    const int gID  = lane >> 2;
    const int tig  = lane & 3;
    const int wrow = warp * 16;

    extern __shared__ char smc[];
    const uint32_t sbase = smem_u32(smc);
    __half* Psh = (__half*)(smc + 2 * ATT_STAGE);
    const uint32_t psbase = sbase + 2 * ATT_STAGE;

    const float scale = 0.08838834764831845f;

    // ldmatrix per-lane decomposition (validated in gemm_core_h)
    const int l7    = lane & 7;
    const int aRowL = l7 + ((lane >> 3) & 1) * 8;
    const int aChO  = lane >> 4;
    const int bRowL = l7 + (lane >> 4) * 8;
    const int bChO  = (lane >> 3) & 1;

    auto fill = [&](int buf, int kb) {
        {
            const int r  = tid >> 2;
            const uint32_t kdst = sbase + buf * ATT_STAGE + r * 256;
            const __half* ksrc = Kh + (size_t)(kb * BKV + r) * (NKV * HD) + hk * HD;
#pragma unroll
            for (int j = 0; j < 4; j++) {
                const int ch = (tid & 3) * 4 + j;
                cp16(kdst + (uint32_t)((ch ^ (r & 7)) << 4), ksrc + ch * 8);
            }
        }
        {
            const int r  = tid >> 1;
            const uint32_t vdst = sbase + buf * ATT_STAGE + 16384 + r * 128;
            const __half* vsrc = Vt + (size_t)(hk * HD + r) * SEQ + kb * BKV;
#pragma unroll
            for (int j = 0; j < 4; j++) {
                const int ch = (tid & 1) * 4 + j;
                cp16(vdst + (uint32_t)((ch ^ (r & 7)) << 4), vsrc + ch * 8);
            }
        }
    };

    // ---- Q fragments: load raw, RoPE in registers, pack fp16 ----
    uint32_t qf[8][4];
    {
        const int s0 = qb * BQ + wrow + gID;
        const int s1 = s0 + 8;
        const float* q0 = Q + (size_t)s0 * DOUT + h * HD;
        const float* q1 = Q + (size_t)s1 * DOUT + h * HD;

        float r0[8][4], r1[8][4];
#pragma unroll
        for (int kk = 0; kk < 8; kk++) {
            const int k = kk * 16;
            r0[kk][0] = q0[k + 2 * tig];     r0[kk][1] = q0[k + 2 * tig + 1];
            r0[kk][2] = q0[k + 8 + 2 * tig]; r0[kk][3] = q0[k + 9 + 2 * tig];
            r1[kk][0] = q1[k + 2 * tig];     r1[kk][1] = q1[k + 2 * tig + 1];
            r1[kk][2] = q1[k + 8 + 2 * tig]; r1[kk][3] = q1[k + 9 + 2 * tig];
        }
        const int off[4] = {2 * tig, 2 * tig + 1, 8 + 2 * tig, 9 + 2 * tig};
#pragma unroll
        for (int kk = 0; kk < 4; kk++) {
#pragma unroll
            for (int j = 0; j < 4; j++) {
                const int d = kk * 16 + off[j];
                const float cL  = cosT[s0 * HD + d],      sL  = sinT[s0 * HD + d];
                const float cH  = cosT[s0 * HD + d + 64], sH  = sinT[s0 * HD + d + 64];
                const float cL1 = cosT[s1 * HD + d],      sL1 = sinT[s1 * HD + d];
                const float cH1 = cosT[s1 * HD + d + 64], sH1 = sinT[s1 * HD + d + 64];
                float lo, hi;
                lo = r0[kk][j]; hi = r0[kk + 4][j];
                r0[kk][j]     = fmaf(lo, cL, -hi * sL);
                r0[kk + 4][j] = fmaf(hi, cH,  lo * sH);
                lo = r1[kk][j]; hi = r1[kk + 4][j];
                r1[kk][j]     = fmaf(lo, cL1, -hi * sL1);
                r1[kk + 4][j] = fmaf(hi, cH1,  lo * sH1);
            }
        }
#pragma unroll
        for (int kk = 0; kk < 8; kk++) {
            qf[kk][0] = pack_h2(r0[kk][0] * scale, r0[kk][1] * scale);
            qf[kk][1] = pack_h2(r1[kk][0] * scale, r1[kk][1] * scale);
            qf[kk][2] = pack_h2(r0[kk][2] * scale, r0[kk][3] * scale);
            qf[kk][3] = pack_h2(r1[kk][2] * scale, r1[kk][3] * scale);
        }
    }

    float mrow[2] = {-1e30f, -1e30f};
    float lrow[2] = {0.f, 0.f};
    float accO[16][4];
#pragma unroll
    for (int i = 0; i < 16; i++)
#pragma unroll
        for (int j = 0; j < 4; j++) accO[i][j] = 0.f;

    const int nkb = 2 * qb + 2;

    fill(0, 0);
    CP_COMMIT();

    // P a-frag base (constant): rows wrow+aRowL, stride 144B, chunk sel per kk
    const uint32_t pABase = psbase + (uint32_t)((wrow + aRowL) * (PSH * 2));

    for (int kb = 0; kb < nkb; kb++) {
        const int buf = kb & 1;
        CP_WAIT(0);
        __syncthreads();
        if (kb + 1 < nkb) fill((kb + 1) & 1, kb + 1);
        CP_COMMIT();

        const uint32_t kAddr = sbase + buf * ATT_STAGE;
        const uint32_t vAddr = kAddr + 16384;

        // per-lane row bases for ldmatrix (constant per tile)
        uint32_t kB[4], vB[8];
#pragma unroll
        for (int nj = 0; nj < 4; nj++)
            kB[nj] = kAddr + (uint32_t)((nj * 16 + bRowL) * 256);
#pragma unroll
        for (int nj = 0; nj < 8; nj++)
            vB[nj] = vAddr + (uint32_t)((nj * 16 + bRowL) * 128);

        // ---- S = Q @ K^T ----
        float accS[8][4];
#pragma unroll
        for (int i = 0; i < 8; i++)
#pragma unroll
            for (int j = 0; j < 4; j++) accS[i][j] = 0.f;

#pragma unroll
        for (int kk = 0; kk < 8; kk++) {
            const uint32_t swB = (uint32_t)(((2 * kk + bChO) ^ l7) << 4);
#pragma unroll
            for (int nj = 0; nj < 4; nj++) {
                uint32_t tmp[4];
                ldsm4(tmp, kB[nj] + swB);
                mma_f16(accS[2 * nj],     qf[kk], tmp);
                mma_f16(accS[2 * nj + 1], qf[kk], tmp + 2);
            }
        }

        // ---- causal mask ----
        if (kb >= 2 * qb) {
            const int q0 = qb * BQ + wrow + gID;
            const int q1 = q0 + 8;
#pragma unroll
            for (int nt = 0; nt < 8; nt++) {
                const int kg = kb * BKV + nt * 8 + 2 * tig;
                if (kg > q0)     accS[nt][0] = -1e30f;
                if (kg + 1 > q0) accS[nt][1] = -1e30f;
                if (kg > q1)     accS[nt][2] = -1e30f;
                if (kg + 1 > q1) accS[nt][3] = -1e30f;
            }
        }

        // ---- online softmax (fp32) ----
        float mx0 = -1e30f, mx1 = -1e30f;
#pragma unroll
        for (int nt = 0; nt < 8; nt++) {
            mx0 = fmaxf(mx0, fmaxf(accS[nt][0], accS[nt][1]));
            mx1 = fmaxf(mx1, fmaxf(accS[nt][2], accS[nt][3]));
        }
        mx0 = fmaxf(mx0, __shfl_xor_sync(0xffffffffu, mx0, 1));
        mx0 = fmaxf(mx0, __shfl_xor_sync(0xffffffffu, mx0, 2));
        mx1 = fmaxf(mx1, __shfl_xor_sync(0xffffffffu, mx1, 1));
        mx1 = fmaxf(mx1, __shfl_xor_sync(0xffffffffu, mx1, 2));

        float mn0 = fmaxf(mrow[0], mx0);
        float mn1 = fmaxf(mrow[1], mx1);
        float al0 = __expf(mrow[0] - mn0);
        float al1 = __expf(mrow[1] - mn1);
        mrow[0] = mn0; mrow[1] = mn1;

        float ls0 = 0.f, ls1 = 0.f;
        const int pr0 = wrow + gID;
#pragma unroll
        for (int nt = 0; nt < 8; nt++) {
            float p0 = __expf(accS[nt][0] - mn0);
            float p1 = __expf(accS[nt][1] - mn0);
            float p2 = __expf(accS[nt][2] - mn1);
            float p3 = __expf(accS[nt][3] - mn1);
            ls0 += p0 + p1;
            ls1 += p2 + p3;
            const int c = nt * 8 + 2 * tig;
            __half2 h0 = __floats2half2_rn(p0, p1);
            __half2 h1 = __floats2half2_rn(p2, p3);
            *(__half2*)(Psh + pr0 * PSH + c)       = h0;
            *(__half2*)(Psh + (pr0 + 8) * PSH + c) = h1;
        }
        ls0 += __shfl_xor_sync(0xffffffffu, ls0, 1);
        ls0 += __shfl_xor_sync(0xffffffffu, ls0, 2);
        ls1 += __shfl_xor_sync(0xffffffffu, ls1, 1);
        ls1 += __shfl_xor_sync(0xffffffffu, ls1, 2);
        lrow[0] = lrow[0] * al0 + ls0;
        lrow[1] = lrow[1] * al1 + ls1;

#pragma unroll
        for (int nt = 0; nt < 16; nt++) {
            accO[nt][0] *= al0; accO[nt][1] *= al0;
            accO[nt][2] *= al1; accO[nt][3] *= al1;
        }
        __syncwarp();   // Ps rows are warp-private

        // ---- O += P @ V ----
#pragma unroll
        for (int kk = 0; kk < 4; kk++) {
            uint32_t a[4];
            ldsm4(a, pABase + (uint32_t)((2 * kk + aChO) << 4));
            const uint32_t swB = (uint32_t)(((2 * kk + bChO) ^ l7) << 4);
#pragma unroll
            for (int nj = 0; nj < 8; nj++) {
                uint32_t tmp[4];
                ldsm4(tmp, vB[nj] + swB);
                mma_f16(accO[2 * nj],     a, tmp);
                mma_f16(accO[2 * nj + 1], a, tmp + 2);
            }
        }
    }

    const float li0 = 1.f / lrow[0];
    const float li1 = 1.f / lrow[1];
    const int r0 = qb * BQ + wrow + gID;
    const int r1 = r0 + 8;
#pragma unroll
    for (int nt = 0; nt < 16; nt++) {
        const int c = h * HD + nt * 8 + 2 * tig;
        __half2 h0 = __floats2half2_rn(accO[nt][0] * li0, accO[nt][1] * li0);
        __half2 h1 = __floats2half2_rn(accO[nt][2] * li1, accO[nt][3] * li1);
        *(__half2*)(ctx + (size_t)r0 * DOUT + c) = h0;
        *(__half2*)(ctx + (size_t)r1 * DOUT + c) = h1;
    }
}

// ---------------------------------------------------------------------------
// Launch
// ---------------------------------------------------------------------------
extern "C" void kernel_launch(void* const* d_in, const int* in_sizes, int n_in,
                              void* d_out, int out_size)
{
    const float* x    = (const float*)d_in[0];
    const float* cosT = (const float*)d_in[1];
    const float* sinT = (const float*)d_in[2];
    const float* Wq   = (const float*)d_in[3];
    const float* Wk   = (const float*)d_in[4];
    const float* Wv   = (const float*)d_in[5];
    const float* Wo   = (const float*)d_in[6];
    float* out = (float*)d_out;

    float *Qp, *Kp;
    __half *Vhp, *Kph, *Vtp, *Cph, *xh, *Wqh, *Wkh, *Wvh, *Woh;
    cudaGetSymbolAddress((void**)&Qp, g_Q);
    cudaGetSymbolAddress((void**)&Kp, g_K);
    cudaGetSymbolAddress((void**)&Vhp, g_Vh);
    cudaGetSymbolAddress((void**)&Kph, g_Kh);
    cudaGetSymbolAddress((void**)&Vtp, g_Vth);
    cudaGetSymbolAddress((void**)&Cph, g_ctxh);
    cudaGetSymbolAddress((void**)&xh, g_xh);
    cudaGetSymbolAddress((void**)&Wqh, g_Wqh);
    cudaGetSymbolAddress((void**)&Wkh, g_Wkh);
    cudaGetSymbolAddress((void**)&Wvh, g_Wvh);
    cudaGetSymbolAddress((void**)&Woh, g_Woh);

    cudaFuncSetAttribute(gemm_qkv, cudaFuncAttributeMaxDynamicSharedMemorySize, GEMM_SMEM);
    cudaFuncSetAttribute(gemm_nt,  cudaFuncAttributeMaxDynamicSharedMemorySize, GEMM_SMEM);
    cudaFuncSetAttribute(attn_mma, cudaFuncAttributeMaxDynamicSharedMemorySize, ATT_SMEM);

    // Batched fp32 -> fp16 conversion
    round_f16_all<<<2048, 256>>>(x, Wq, Wk, Wv, Wo, xh, Wqh, Wkh, Wvh, Woh);

    // Fused QKV projection (V written fp16 directly)
    gemm_qkv<<<dim3(48, SEQ / 128), 128, GEMM_SMEM>>>(xh, Wqh, Wkh, Wvh, Qp, Kp, Vhp);

    // Merged K-RoPE + V-transpose
    ropek_vtrans<<<KB_ROPE + KB_VT_X * KB_VT_Y, 256>>>(Kp, Kph, Vhp, Vtp, cosT, sinT);

    // fp16 flash attention (fused Q-RoPE, ldmatrix fragments)
    attn_mma<<<dim3(SEQ / BQ, NH), 256, ATT_SMEM>>>(Qp, Kph, Vtp, Cph, cosT, sinT);

    // Output projection
    gemm_nt<<<dim3(DOUT / 128, SEQ / 128), 128, GEMM_SMEM>>>(Cph, Woh, out, DIN, DOUT);
}